// round 6
// baseline (speedup 1.0000x reference)
#include <cuda_runtime.h>
#include <cstdint>

#define NPTS    6890
#define BF      (NPTS * 3)      // 20670 floats per batch per tensor
#define HALF0   10332           // rank0 floats (3444 points); rank1 = 10338 (3446 points)
#define THREADS 512
#define NWARPS  (THREADS / 32)
#define NSTAGE  4
#define CHUNK   2584            // floats per load stage (10336 B, 16B-multiple)

// smem layout (float offsets), per CTA ~84 KB -> 2 CTAs/SM
#define SM_PRED  0
#define SM_GT    10344
#define SM_RED   20688          // NWARPS*16 = 256
#define SM_STAT  20944          // 16 (this CTA's partial sums)
#define SM_STATC 20960          // 16 (combined sums)
#define SM_PRM   20976          // 12 (scale*R 9, t 3)
#define SM_MBAR  20988          // byte 83952, 8B aligned; 4 mbarriers
#define SMEM_FLOATS (20988 + 8)
#define SMEM_BYTES  (SMEM_FLOATS * 4)

__device__ __forceinline__ uint32_t smem_addr(const void* p) {
    return (uint32_t)__cvta_generic_to_shared(p);
}

__device__ __forceinline__ void accum_pt(float* a,
                                         float p0, float p1, float p2,
                                         float g0, float g1, float g2) {
    a[0] += p0; a[1] += p1; a[2] += p2;
    a[3] += g0; a[4] += g1; a[5] += g2;
    a[6] = fmaf(p0, p0, fmaf(p1, p1, fmaf(p2, p2, a[6])));
    a[7]  = fmaf(p0, g0, a[7]);
    a[8]  = fmaf(p0, g1, a[8]);
    a[9]  = fmaf(p0, g2, a[9]);
    a[10] = fmaf(p1, g0, a[10]);
    a[11] = fmaf(p1, g1, a[11]);
    a[12] = fmaf(p1, g2, a[12]);
    a[13] = fmaf(p2, g0, a[13]);
    a[14] = fmaf(p2, g1, a[14]);
    a[15] = fmaf(p2, g2, a[15]);
}

__device__ __forceinline__ void mbar_wait0(uint32_t mbarA) {
    uint32_t done = 0;
    while (!done) {
        asm volatile("{\n\t.reg .pred p;\n\t"
                     "mbarrier.try_wait.parity.acquire.cta.shared::cta.b64 p, [%1], 0, 0x989680;\n\t"
                     "selp.b32 %0, 1, 0, p;\n\t}"
                     : "=r"(done) : "r"(mbarA) : "memory");
    }
}

__global__ void __launch_bounds__(THREADS, 1)
procrustes_l1_kernel(const float* __restrict__ pred,
                     const float* __restrict__ gt,
                     float* __restrict__ out) {
    extern __shared__ float sm[];
    float* predS = sm + SM_PRED;
    float* gtS   = sm + SM_GT;
    float* redS  = sm + SM_RED;
    float* statS = sm + SM_STAT;
    float* statC = sm + SM_STATC;
    float* prm   = sm + SM_PRM;

    const int tid = threadIdx.x;
    const unsigned rank = blockIdx.x & 1u;             // cluster rank (cluster dim = 2)
    const int b = (int)(blockIdx.x >> 1);
    const size_t gstart = (size_t)b * BF + (rank ? HALF0 : 0);
    const int F  = rank ? (BF - HALF0) : HALF0;        // 10338 / 10332 floats
    const int NU = F / 6;                              // 6-float units (2 points)
    const int pad = (int)(gstart & 3);                 // 0 or 2
    const int F_load = (pad + F + 3) & ~3;             // padded load size (16B mult)

    int E[NSTAGE + 1];
    E[0] = 0; E[1] = CHUNK; E[2] = 2 * CHUNK; E[3] = 3 * CHUNK; E[4] = F_load;

    const uint32_t mbar0 = smem_addr(sm + SM_MBAR);

    if (tid == 0) {
#pragma unroll
        for (int s = 0; s < NSTAGE; s++)
            asm volatile("mbarrier.init.shared.b64 [%0], 1;" :: "r"(mbar0 + 8u * s) : "memory");
    }
    __syncthreads();

    // --- chunked TMA loads: per stage, pred chunk + gt chunk ---
    if (tid == 0) {
        const float* srcP = pred + (gstart - (size_t)pad);
        const float* srcG = gt   + (gstart - (size_t)pad);
#pragma unroll
        for (int s = 0; s < NSTAGE; s++) {
            uint32_t cb = (uint32_t)(E[s + 1] - E[s]) * 4u;
            uint32_t mb = mbar0 + 8u * s;
            asm volatile("mbarrier.arrive.expect_tx.shared.b64 _, [%0], %1;"
                         :: "r"(mb), "r"(2u * cb) : "memory");
            asm volatile("cp.async.bulk.shared::cluster.global.mbarrier::complete_tx::bytes [%0], [%1], %2, [%3];"
                         :: "r"(smem_addr(predS + E[s])), "l"(srcP + E[s]), "r"(cb), "r"(mb) : "memory");
            asm volatile("cp.async.bulk.shared::cluster.global.mbarrier::complete_tx::bytes [%0], [%1], %2, [%3];"
                         :: "r"(smem_addr(gtS + E[s])), "l"(srcG + E[s]), "r"(cb), "r"(mb) : "memory");
        }
    }

    // --- Pass A: 16-value reduction, overlapped with the staged loads ---
    float acc[16];
#pragma unroll
    for (int i = 0; i < 16; i++) acc[i] = 0.f;

    const float* pS = predS + pad;
    const float* gS = gtS + pad;
    int uPrev = 0;
    for (int s = 0; s < NSTAGE; s++) {
        mbar_wait0(mbar0 + 8u * s);
        int uEnd = (E[s + 1] - pad) / 6;
        if (uEnd > NU) uEnd = NU;
        for (int u = uPrev + tid; u < uEnd; u += THREADS) {
            int base = 6 * u;
            float2 pa = *(const float2*)(pS + base);
            float2 pb = *(const float2*)(pS + base + 2);
            float2 pc = *(const float2*)(pS + base + 4);
            float2 ga = *(const float2*)(gS + base);
            float2 gb = *(const float2*)(gS + base + 2);
            float2 gc = *(const float2*)(gS + base + 4);
            accum_pt(acc, pa.x, pa.y, pb.x, ga.x, ga.y, gb.x);
            accum_pt(acc, pb.y, pc.x, pc.y, gb.y, gc.x, gc.y);
        }
        uPrev = uEnd;
    }

    // warp reduce 16 values
#pragma unroll
    for (int i = 0; i < 16; i++) {
        float v = acc[i];
        v += __shfl_down_sync(0xffffffffu, v, 16);
        v += __shfl_down_sync(0xffffffffu, v, 8);
        v += __shfl_down_sync(0xffffffffu, v, 4);
        v += __shfl_down_sync(0xffffffffu, v, 2);
        v += __shfl_down_sync(0xffffffffu, v, 1);
        acc[i] = v;
    }
    const int lane = tid & 31;
    const int wp = tid >> 5;
    if (lane == 0) {
#pragma unroll
        for (int i = 0; i < 16; i++) redS[wp * 16 + i] = acc[i];
    }
    __syncthreads();
    if (tid < 16) {
        float s = redS[tid];
#pragma unroll
        for (int w = 1; w < NWARPS; w++) s += redS[w * 16 + tid];
        statS[tid] = s;                 // this CTA's partial (peer reads this)
    }
    __syncthreads();

    // --- cluster exchange of partial sums (DSMEM) ---
    asm volatile("barrier.cluster.arrive.aligned;" ::: "memory");
    asm volatile("barrier.cluster.wait.aligned;"   ::: "memory");
    if (tid < 16) {
        uint32_t la = smem_addr(statS + tid);
        uint32_t pa_;
        asm volatile("mapa.shared::cluster.u32 %0, %1, %2;" : "=r"(pa_) : "r"(la), "r"(rank ^ 1u));
        float pv;
        asm volatile("ld.shared::cluster.f32 %0, [%1];" : "=f"(pv) : "r"(pa_) : "memory");
        statC[tid] = statS[tid] + pv;   // commutative -> bit-identical on both ranks
    }
    asm volatile("barrier.cluster.arrive.aligned;" ::: "memory");   // paired with wait at end
    __syncthreads();

    // --- Thread 0: 3x3 Procrustes solve (fp32 Jacobi, overflow-safe math) ---
    if (tid == 0) {
        const float fN = (float)NPTS;
        const float invN = 1.0f / fN;
        float mu1[3], mu2[3];
#pragma unroll
        for (int i = 0; i < 3; i++) { mu1[i] = statC[i] * invN; mu2[i] = statC[3 + i] * invN; }

        float K[3][3];
#pragma unroll
        for (int i = 0; i < 3; i++)
#pragma unroll
            for (int j = 0; j < 3; j++)
                K[i][j] = statC[7 + 3 * i + j] - fN * mu1[i] * mu2[j] + 1e-8f;

        float var1 = statC[6] - fN * (mu1[0]*mu1[0] + mu1[1]*mu1[1] + mu1[2]*mu1[2]);

        float A[3][3];
#pragma unroll
        for (int i = 0; i < 3; i++)
#pragma unroll
            for (int j = 0; j < 3; j++)
                A[i][j] = K[0][i]*K[0][j] + K[1][i]*K[1][j] + K[2][i]*K[2][j];

        float V[3][3] = { {1.f,0.f,0.f}, {0.f,1.f,0.f}, {0.f,0.f,1.f} };

        for (int sweep = 0; sweep < 6; sweep++) {
#pragma unroll
            for (int pair = 0; pair < 3; pair++) {
                int p = (pair == 2) ? 1 : 0;
                int q = (pair == 0) ? 1 : 2;
                float apq = A[p][q];
                if (fabsf(apq) > 1e-18f) {
                    // overflow-safe: tau may be huge; sqrtf(inf)=inf -> tt->0 (rotation skip)
                    float tau = (A[q][q] - A[p][p]) / (2.f * apq);
                    float tt = copysignf(1.f, tau) / (fabsf(tau) + sqrtf(fmaf(tau, tau, 1.f)));
                    float c = rsqrtf(fmaf(tt, tt, 1.f));
                    float s = tt * c;
#pragma unroll
                    for (int k = 0; k < 3; k++) {
                        float akp = A[k][p], akq = A[k][q];
                        A[k][p] = c*akp - s*akq;
                        A[k][q] = s*akp + c*akq;
                    }
#pragma unroll
                    for (int k = 0; k < 3; k++) {
                        float apk = A[p][k], aqk = A[q][k];
                        A[p][k] = c*apk - s*aqk;
                        A[q][k] = s*apk + c*aqk;
                    }
#pragma unroll
                    for (int k = 0; k < 3; k++) {
                        float vkp = V[k][p], vkq = V[k][q];
                        V[k][p] = c*vkp - s*vkq;
                        V[k][q] = s*vkp + c*vkq;
                    }
                }
            }
        }

        float dd[3] = { A[0][0], A[1][1], A[2][2] };
        int oo[3] = { 0, 1, 2 };
        if (dd[oo[0]] < dd[oo[1]]) { int t = oo[0]; oo[0] = oo[1]; oo[1] = t; }
        if (dd[oo[0]] < dd[oo[2]]) { int t = oo[0]; oo[0] = oo[2]; oo[2] = t; }
        if (dd[oo[1]] < dd[oo[2]]) { int t = oo[1]; oo[1] = oo[2]; oo[2] = t; }

        float v0[3], v1[3], v2[3];
#pragma unroll
        for (int i = 0; i < 3; i++) { v0[i] = V[i][oo[0]]; v1[i] = V[i][oo[1]]; v2[i] = V[i][oo[2]]; }
        float det =
            v0[0]*(v1[1]*v2[2] - v1[2]*v2[1]) -
            v0[1]*(v1[0]*v2[2] - v1[2]*v2[0]) +
            v0[2]*(v1[0]*v2[1] - v1[1]*v2[0]);
        if (det < 0.f) { v2[0] = -v2[0]; v2[1] = -v2[1]; v2[2] = -v2[2]; }

        float Kv0[3], Kv1[3];
#pragma unroll
        for (int i = 0; i < 3; i++) {
            Kv0[i] = K[i][0]*v0[0] + K[i][1]*v0[1] + K[i][2]*v0[2];
            Kv1[i] = K[i][0]*v1[0] + K[i][1]*v1[1] + K[i][2]*v1[2];
        }
        float r0 = rsqrtf(Kv0[0]*Kv0[0] + Kv0[1]*Kv0[1] + Kv0[2]*Kv0[2] + 1e-30f);
        float u0[3] = { Kv0[0]*r0, Kv0[1]*r0, Kv0[2]*r0 };
        float d01 = u0[0]*Kv1[0] + u0[1]*Kv1[1] + u0[2]*Kv1[2];
        float u1r[3] = { Kv1[0]-d01*u0[0], Kv1[1]-d01*u0[1], Kv1[2]-d01*u0[2] };
        float r1 = rsqrtf(u1r[0]*u1r[0] + u1r[1]*u1r[1] + u1r[2]*u1r[2] + 1e-30f);
        float u1[3] = { u1r[0]*r1, u1r[1]*r1, u1r[2]*r1 };
        float w[3] = { u0[1]*u1[2] - u0[2]*u1[1],
                       u0[2]*u1[0] - u0[0]*u1[2],
                       u0[0]*u1[1] - u0[1]*u1[0] };

        float R[3][3];
#pragma unroll
        for (int i = 0; i < 3; i++)
#pragma unroll
            for (int j = 0; j < 3; j++)
                R[i][j] = v0[i]*u0[j] + v1[i]*u1[j] + v2[i]*w[j];

        float tr = 0.f;
#pragma unroll
        for (int i = 0; i < 3; i++)
#pragma unroll
            for (int j = 0; j < 3; j++)
                tr += R[i][j] * K[j][i];
        float scale = tr / var1;

#pragma unroll
        for (int i = 0; i < 3; i++)
#pragma unroll
            for (int j = 0; j < 3; j++)
                R[i][j] *= scale;
#pragma unroll
        for (int i = 0; i < 3; i++)
            prm[9 + i] = mu2[i] - (R[i][0]*mu1[0] + R[i][1]*mu1[1] + R[i][2]*mu1[2]);
#pragma unroll
        for (int i = 0; i < 3; i++)
#pragma unroll
            for (int j = 0; j < 3; j++)
                prm[3 * i + j] = R[i][j];
    }
    __syncthreads();

    // --- Pass B: out = |Rs*p + t - g| in-place into predS ---
    float Rs[9], tv[3];
#pragma unroll
    for (int i = 0; i < 9; i++) Rs[i] = prm[i];
    tv[0] = prm[9]; tv[1] = prm[10]; tv[2] = prm[11];

    float* pW = predS + pad;
    for (int u = tid; u < NU; u += THREADS) {
        int base = 6 * u;
        float2 pa = *(const float2*)(pW + base);
        float2 pb = *(const float2*)(pW + base + 2);
        float2 pc = *(const float2*)(pW + base + 4);
        float2 ga = *(const float2*)(gS + base);
        float2 gb = *(const float2*)(gS + base + 2);
        float2 gc = *(const float2*)(gS + base + 4);

        float p0x = pa.x, p0y = pa.y, p0z = pb.x;
        float p1x = pb.y, p1y = pc.x, p1z = pc.y;

        float o0x = fabsf(fmaf(Rs[0], p0x, fmaf(Rs[1], p0y, fmaf(Rs[2], p0z, tv[0]))) - ga.x);
        float o0y = fabsf(fmaf(Rs[3], p0x, fmaf(Rs[4], p0y, fmaf(Rs[5], p0z, tv[1]))) - ga.y);
        float o0z = fabsf(fmaf(Rs[6], p0x, fmaf(Rs[7], p0y, fmaf(Rs[8], p0z, tv[2]))) - gb.x);
        float o1x = fabsf(fmaf(Rs[0], p1x, fmaf(Rs[1], p1y, fmaf(Rs[2], p1z, tv[0]))) - gb.y);
        float o1y = fabsf(fmaf(Rs[3], p1x, fmaf(Rs[4], p1y, fmaf(Rs[5], p1z, tv[1]))) - gc.x);
        float o1z = fabsf(fmaf(Rs[6], p1x, fmaf(Rs[7], p1y, fmaf(Rs[8], p1z, tv[2]))) - gc.y);

        *(float2*)(pW + base)     = make_float2(o0x, o0y);
        *(float2*)(pW + base + 2) = make_float2(o0z, o1x);
        *(float2*)(pW + base + 4) = make_float2(o1y, o1z);
    }
    __syncthreads();

    // --- Store: TMA bulk aligned interior + up to 4 scalar edge floats ---
    if (tid == 0) {
        int a  = pad ? 2 : 0;                // front misaligned floats
        int bb = (pad + F) & 3;              // back misaligned floats
        int L  = F - a - bb;                 // interior length (mult of 4)
        asm volatile("fence.proxy.async.shared::cta;" ::: "memory");
        asm volatile("cp.async.bulk.global.shared::cta.bulk_group [%0], [%1], %2;"
                     :: "l"(out + gstart + a), "r"(smem_addr(predS + pad + a)),
                        "r"((uint32_t)L * 4u) : "memory");
        asm volatile("cp.async.bulk.commit_group;" ::: "memory");
        for (int i = 0; i < a; i++)  out[gstart + i]         = predS[pad + i];
        for (int i = 0; i < bb; i++) out[gstart + F - 1 - i] = predS[pad + F - 1 - i];
        asm volatile("cp.async.bulk.wait_group 0;" ::: "memory");
    }

    // pair exit safety: peer must finish reading our statS before we exit
    asm volatile("barrier.cluster.wait.aligned;" ::: "memory");
}

extern "C" void kernel_launch(void* const* d_in, const int* in_sizes, int n_in,
                              void* d_out, int out_size) {
    const float* pred = (const float*)d_in[0];
    const float* gt   = (const float*)d_in[1];
    float* out = (float*)d_out;
    int B = in_sizes[0] / BF;   // 1024

    cudaFuncSetAttribute(procrustes_l1_kernel,
                         cudaFuncAttributeMaxDynamicSharedMemorySize, SMEM_BYTES);

    cudaLaunchConfig_t cfg = {};
    cfg.gridDim = dim3((unsigned)(2 * B), 1, 1);
    cfg.blockDim = dim3(THREADS, 1, 1);
    cfg.dynamicSmemBytes = SMEM_BYTES;
    cudaLaunchAttribute attrs[1];
    attrs[0].id = cudaLaunchAttributeClusterDimension;
    attrs[0].val.clusterDim.x = 2;
    attrs[0].val.clusterDim.y = 1;
    attrs[0].val.clusterDim.z = 1;
    cfg.attrs = attrs;
    cfg.numAttrs = 1;
    cudaLaunchKernelEx(&cfg, procrustes_l1_kernel, pred, gt, out);
}

// round 8
// speedup vs baseline: 1.2504x; 1.2504x over previous
#include <cuda_runtime.h>
#include <cstdint>

#define NPTS    6890
#define BF      20670           // floats per batch per tensor
#define THREADS 256
#define NWARPS  8
#define CHUNK   2076            // ring-slot size in floats (8304 B, mult of 12 & 16B)
#define NB      3               // ring depth
#define F_LOAD  20672           // padded stream length (covers pad 0 or 2)
#define NC      10              // chunks per batch
#define NU      3445            // 6-float units (2 points each)

// smem layout (float offsets); ~50.5 KB/CTA -> 4 CTAs/SM
#define SM_PRED 0
#define SM_GT   (NB * CHUNK)                 // 6228
#define SM_RED  (2 * NB * CHUNK)             // 12456
#define SM_STAT (SM_RED + NWARPS * 16)       // 12584
#define SM_PRM  (SM_STAT + 16)               // 12600
#define SM_MBAR (SM_PRM + 12)                // 12612 -> byte 50448 (8B aligned)
#define SMEM_FLOATS (SM_MBAR + 2 * NB)
#define SMEM_BYTES  (SMEM_FLOATS * 4)

__device__ __forceinline__ uint32_t smem_addr(const void* p) {
    return (uint32_t)__cvta_generic_to_shared(p);
}

__device__ __forceinline__ void mbar_wait(uint32_t mbarA, uint32_t parity) {
    uint32_t done = 0;
    while (!done) {
        asm volatile("{\n\t.reg .pred p;\n\t"
                     "mbarrier.try_wait.parity.acquire.cta.shared::cta.b64 p, [%1], %2, 0x989680;\n\t"
                     "selp.b32 %0, 1, 0, p;\n\t}"
                     : "=r"(done) : "r"(mbarA), "r"(parity) : "memory");
    }
}

// chunk boundary in padded-stream float coords: E[0]=0, E[c]=EF+(c-1)*CHUNK capped
__device__ __forceinline__ int Eof(int c, int EF) {
    if (c <= 0) return 0;
    int e = EF + (c - 1) * CHUNK;
    return e < F_LOAD ? e : F_LOAD;
}

__device__ __forceinline__ void issue_load(int c, int EF,
                                           const float* srcP, const float* srcG,
                                           float* predS, float* gtS, uint32_t mbar0) {
    int e0 = Eof(c, EF), e1 = Eof(c + 1, EF);
    uint32_t bytes = (uint32_t)(e1 - e0) * 4u;
    uint32_t mb = mbar0 + 8u * (uint32_t)(c % NB);
    asm volatile("mbarrier.arrive.expect_tx.shared.b64 _, [%0], %1;"
                 :: "r"(mb), "r"(2u * bytes) : "memory");
    asm volatile("cp.async.bulk.shared::cluster.global.mbarrier::complete_tx::bytes [%0], [%1], %2, [%3];"
                 :: "r"(smem_addr(predS + (c % NB) * CHUNK)), "l"(srcP + e0), "r"(bytes), "r"(mb) : "memory");
    asm volatile("cp.async.bulk.shared::cluster.global.mbarrier::complete_tx::bytes [%0], [%1], %2, [%3];"
                 :: "r"(smem_addr(gtS + (c % NB) * CHUNK)), "l"(srcG + e0), "r"(bytes), "r"(mb) : "memory");
}

__device__ __forceinline__ void accum_pt(float* a,
                                         float p0, float p1, float p2,
                                         float g0, float g1, float g2) {
    a[0] += p0; a[1] += p1; a[2] += p2;
    a[3] += g0; a[4] += g1; a[5] += g2;
    a[6] = fmaf(p0, p0, fmaf(p1, p1, fmaf(p2, p2, a[6])));
    a[7]  = fmaf(p0, g0, a[7]);
    a[8]  = fmaf(p0, g1, a[8]);
    a[9]  = fmaf(p0, g2, a[9]);
    a[10] = fmaf(p1, g0, a[10]);
    a[11] = fmaf(p1, g1, a[11]);
    a[12] = fmaf(p1, g2, a[12]);
    a[13] = fmaf(p2, g0, a[13]);
    a[14] = fmaf(p2, g1, a[14]);
    a[15] = fmaf(p2, g2, a[15]);
}

__global__ void __launch_bounds__(THREADS, 4)
procrustes_l1_kernel(const float* __restrict__ pred,
                     const float* __restrict__ gt,
                     float* __restrict__ out) {
    extern __shared__ float sm[];
    float* predS = sm + SM_PRED;
    float* gtS   = sm + SM_GT;
    float* redS  = sm + SM_RED;
    float* statS = sm + SM_STAT;
    float* prm   = sm + SM_PRM;

    const int tid = threadIdx.x;
    const int b = (int)blockIdx.x;
    const size_t gstart = (size_t)b * BF;
    const int pad = (int)(gstart & 3);          // 0 (even b) or 2 (odd b)
    const int EF = pad ? (CHUNK - 4) : CHUNK;   // first-chunk size keeps E ≡ pad (mod 6), ≡0 (mod 4)

    const float* srcP = pred + (gstart - (size_t)pad);
    const float* srcG = gt   + (gstart - (size_t)pad);
    const uint32_t mbar0 = smem_addr(sm + SM_MBAR);

    if (tid == 0) {
#pragma unroll
        for (int s = 0; s < NB; s++)
            asm volatile("mbarrier.init.shared.b64 [%0], 1;" :: "r"(mbar0 + 8u * s) : "memory");
    }
    __syncthreads();

    // prologue: fill the ring
    if (tid == 0) {
#pragma unroll
        for (int c = 0; c < NB; c++) issue_load(c, EF, srcP, srcG, predS, gtS, mbar0);
    }

    // ---------------- Pass A: streamed 16-value reduction ----------------
    float acc[16];
#pragma unroll
    for (int i = 0; i < 16; i++) acc[i] = 0.f;

    for (int c = 0; c < NC; c++) {
        mbar_wait(mbar0 + 8u * (c % NB), (uint32_t)((c / NB) & 1));
        int e0 = Eof(c, EF), e1 = Eof(c + 1, EF);
        const float* pc = predS + (c % NB) * CHUNK - e0;
        const float* gc = gtS   + (c % NB) * CHUNK - e0;
        int uS = (e0 - pad + 5) / 6;
        int uE = (e1 - pad) / 6; if (uE > NU) uE = NU;
        for (int u = uS + tid; u < uE; u += THREADS) {
            int l = pad + 6 * u;
            float2 pa = *(const float2*)(pc + l);
            float2 pb = *(const float2*)(pc + l + 2);
            float2 pcc = *(const float2*)(pc + l + 4);
            float2 ga = *(const float2*)(gc + l);
            float2 gb = *(const float2*)(gc + l + 2);
            float2 gcc = *(const float2*)(gc + l + 4);
            accum_pt(acc, pa.x, pa.y, pb.x, ga.x, ga.y, gb.x);
            accum_pt(acc, pb.y, pcc.x, pcc.y, gb.y, gcc.x, gcc.y);
        }
        __syncthreads();
        if (tid == 0 && c + NB < NC) issue_load(c + NB, EF, srcP, srcG, predS, gtS, mbar0);
    }

    // prefetch pass-B chunks 0..2 now (they complete while we reduce + solve)
    if (tid == 0) {
#pragma unroll
        for (int c = 0; c < NB; c++) issue_load(c, EF, srcP, srcG, predS, gtS, mbar0);
    }

    // warp + block reduction of the 16 stats
#pragma unroll
    for (int i = 0; i < 16; i++) {
        float v = acc[i];
        v += __shfl_down_sync(0xffffffffu, v, 16);
        v += __shfl_down_sync(0xffffffffu, v, 8);
        v += __shfl_down_sync(0xffffffffu, v, 4);
        v += __shfl_down_sync(0xffffffffu, v, 2);
        v += __shfl_down_sync(0xffffffffu, v, 1);
        acc[i] = v;
    }
    const int lane = tid & 31;
    const int wp = tid >> 5;
    if (lane == 0) {
#pragma unroll
        for (int i = 0; i < 16; i++) redS[wp * 16 + i] = acc[i];
    }
    __syncthreads();
    if (tid < 16) {
        float s = redS[tid];
#pragma unroll
        for (int w = 1; w < NWARPS; w++) s += redS[w * 16 + tid];
        statS[tid] = s;
    }
    __syncthreads();

    // ---------------- Thread 0: 3x3 Procrustes solve (overflow-safe fp32 Jacobi) ----
    if (tid == 0) {
        const float fN = (float)NPTS;
        const float invN = 1.0f / fN;
        float mu1[3], mu2[3];
#pragma unroll
        for (int i = 0; i < 3; i++) { mu1[i] = statS[i] * invN; mu2[i] = statS[3 + i] * invN; }

        float K[3][3];
#pragma unroll
        for (int i = 0; i < 3; i++)
#pragma unroll
            for (int j = 0; j < 3; j++)
                K[i][j] = statS[7 + 3 * i + j] - fN * mu1[i] * mu2[j] + 1e-8f;

        float var1 = statS[6] - fN * (mu1[0]*mu1[0] + mu1[1]*mu1[1] + mu1[2]*mu1[2]);

        float A[3][3];
#pragma unroll
        for (int i = 0; i < 3; i++)
#pragma unroll
            for (int j = 0; j < 3; j++)
                A[i][j] = K[0][i]*K[0][j] + K[1][i]*K[1][j] + K[2][i]*K[2][j];

        float V[3][3] = { {1.f,0.f,0.f}, {0.f,1.f,0.f}, {0.f,0.f,1.f} };

        for (int sweep = 0; sweep < 6; sweep++) {
#pragma unroll
            for (int pair = 0; pair < 3; pair++) {
                int p = (pair == 2) ? 1 : 0;
                int q = (pair == 0) ? 1 : 2;
                float apq = A[p][q];
                if (fabsf(apq) > 1e-18f) {
                    float tau = (A[q][q] - A[p][p]) / (2.f * apq);
                    float tt = copysignf(1.f, tau) / (fabsf(tau) + sqrtf(fmaf(tau, tau, 1.f)));
                    float c = rsqrtf(fmaf(tt, tt, 1.f));
                    float s = tt * c;
#pragma unroll
                    for (int k = 0; k < 3; k++) {
                        float akp = A[k][p], akq = A[k][q];
                        A[k][p] = c*akp - s*akq;
                        A[k][q] = s*akp + c*akq;
                    }
#pragma unroll
                    for (int k = 0; k < 3; k++) {
                        float apk = A[p][k], aqk = A[q][k];
                        A[p][k] = c*apk - s*aqk;
                        A[q][k] = s*apk + c*aqk;
                    }
#pragma unroll
                    for (int k = 0; k < 3; k++) {
                        float vkp = V[k][p], vkq = V[k][q];
                        V[k][p] = c*vkp - s*vkq;
                        V[k][q] = s*vkp + c*vkq;
                    }
                }
            }
        }

        float dd[3] = { A[0][0], A[1][1], A[2][2] };
        int oo[3] = { 0, 1, 2 };
        if (dd[oo[0]] < dd[oo[1]]) { int t = oo[0]; oo[0] = oo[1]; oo[1] = t; }
        if (dd[oo[0]] < dd[oo[2]]) { int t = oo[0]; oo[0] = oo[2]; oo[2] = t; }
        if (dd[oo[1]] < dd[oo[2]]) { int t = oo[1]; oo[1] = oo[2]; oo[2] = t; }

        float v0[3], v1[3], v2[3];
#pragma unroll
        for (int i = 0; i < 3; i++) { v0[i] = V[i][oo[0]]; v1[i] = V[i][oo[1]]; v2[i] = V[i][oo[2]]; }
        float det =
            v0[0]*(v1[1]*v2[2] - v1[2]*v2[1]) -
            v0[1]*(v1[0]*v2[2] - v1[2]*v2[0]) +
            v0[2]*(v1[0]*v2[1] - v1[1]*v2[0]);
        if (det < 0.f) { v2[0] = -v2[0]; v2[1] = -v2[1]; v2[2] = -v2[2]; }

        float Kv0[3], Kv1[3];
#pragma unroll
        for (int i = 0; i < 3; i++) {
            Kv0[i] = K[i][0]*v0[0] + K[i][1]*v0[1] + K[i][2]*v0[2];
            Kv1[i] = K[i][0]*v1[0] + K[i][1]*v1[1] + K[i][2]*v1[2];
        }
        float r0 = rsqrtf(Kv0[0]*Kv0[0] + Kv0[1]*Kv0[1] + Kv0[2]*Kv0[2] + 1e-30f);
        float u0[3] = { Kv0[0]*r0, Kv0[1]*r0, Kv0[2]*r0 };
        float d01 = u0[0]*Kv1[0] + u0[1]*Kv1[1] + u0[2]*Kv1[2];
        float u1r[3] = { Kv1[0]-d01*u0[0], Kv1[1]-d01*u0[1], Kv1[2]-d01*u0[2] };
        float r1 = rsqrtf(u1r[0]*u1r[0] + u1r[1]*u1r[1] + u1r[2]*u1r[2] + 1e-30f);
        float u1[3] = { u1r[0]*r1, u1r[1]*r1, u1r[2]*r1 };
        float w[3] = { u0[1]*u1[2] - u0[2]*u1[1],
                       u0[2]*u1[0] - u0[0]*u1[2],
                       u0[0]*u1[1] - u0[1]*u1[0] };

        float R[3][3];
#pragma unroll
        for (int i = 0; i < 3; i++)
#pragma unroll
            for (int j = 0; j < 3; j++)
                R[i][j] = v0[i]*u0[j] + v1[i]*u1[j] + v2[i]*w[j];

        float tr = 0.f;
#pragma unroll
        for (int i = 0; i < 3; i++)
#pragma unroll
            for (int j = 0; j < 3; j++)
                tr += R[i][j] * K[j][i];
        float scale = tr / var1;

#pragma unroll
        for (int i = 0; i < 3; i++)
#pragma unroll
            for (int j = 0; j < 3; j++)
                R[i][j] *= scale;
#pragma unroll
        for (int i = 0; i < 3; i++)
            prm[9 + i] = mu2[i] - (R[i][0]*mu1[0] + R[i][1]*mu1[1] + R[i][2]*mu1[2]);
#pragma unroll
        for (int i = 0; i < 3; i++)
#pragma unroll
            for (int j = 0; j < 3; j++)
                prm[3 * i + j] = R[i][j];
    }
    __syncthreads();

    // ---------------- Pass B: streamed apply + TMA store ----------------
    float Rs[9], tv[3];
#pragma unroll
    for (int i = 0; i < 9; i++) Rs[i] = prm[i];
    tv[0] = prm[9]; tv[1] = prm[10]; tv[2] = prm[11];

    const int tailAligned = (pad + BF) & ~3;    // align-down end of valid stream

    for (int c = 0; c < NC; c++) {
        // parity: slot c%3 was used (4,3,3) times in pass A for slots (0,1,2)
        uint32_t parB = (uint32_t)((((c % NB) == 0 ? 4 : 3) + c / NB) & 1);
        mbar_wait(mbar0 + 8u * (c % NB), parB);
        int e0 = Eof(c, EF), e1 = Eof(c + 1, EF);
        float* pc = predS + (c % NB) * CHUNK - e0;
        const float* gc = gtS + (c % NB) * CHUNK - e0;
        int uS = (e0 - pad + 5) / 6;
        int uE = (e1 - pad) / 6; if (uE > NU) uE = NU;
        for (int u = uS + tid; u < uE; u += THREADS) {
            int l = pad + 6 * u;
            float2 pa = *(const float2*)(pc + l);
            float2 pb = *(const float2*)(pc + l + 2);
            float2 pcc = *(const float2*)(pc + l + 4);
            float2 ga = *(const float2*)(gc + l);
            float2 gb = *(const float2*)(gc + l + 2);
            float2 gcc = *(const float2*)(gc + l + 4);

            float p0x = pa.x, p0y = pa.y, p0z = pb.x;
            float p1x = pb.y, p1y = pcc.x, p1z = pcc.y;

            float o0x = fabsf(fmaf(Rs[0], p0x, fmaf(Rs[1], p0y, fmaf(Rs[2], p0z, tv[0]))) - ga.x);
            float o0y = fabsf(fmaf(Rs[3], p0x, fmaf(Rs[4], p0y, fmaf(Rs[5], p0z, tv[1]))) - ga.y);
            float o0z = fabsf(fmaf(Rs[6], p0x, fmaf(Rs[7], p0y, fmaf(Rs[8], p0z, tv[2]))) - gb.x);
            float o1x = fabsf(fmaf(Rs[0], p1x, fmaf(Rs[1], p1y, fmaf(Rs[2], p1z, tv[0]))) - gb.y);
            float o1y = fabsf(fmaf(Rs[3], p1x, fmaf(Rs[4], p1y, fmaf(Rs[5], p1z, tv[1]))) - gcc.x);
            float o1z = fabsf(fmaf(Rs[6], p1x, fmaf(Rs[7], p1y, fmaf(Rs[8], p1z, tv[2]))) - gcc.y);

            *(float2*)(pc + l)     = make_float2(o0x, o0y);
            *(float2*)(pc + l + 2) = make_float2(o0z, o1x);
            *(float2*)(pc + l + 4) = make_float2(o1y, o1z);
        }
        __syncthreads();
        if (tid == 0) {
            asm volatile("fence.proxy.async.shared::cta;" ::: "memory");
            int sl0 = (c == 0 && pad) ? 4 : e0;                 // skip front misaligned part
            int sl1 = e1 < tailAligned ? e1 : tailAligned;      // trim tail
            uint32_t sb = (uint32_t)(sl1 - sl0) * 4u;
            float* bufB = predS + (c % NB) * CHUNK;             // slot base
            asm volatile("cp.async.bulk.global.shared::cta.bulk_group [%0], [%1], %2;"
                         :: "l"(out + gstart - (size_t)pad + sl0),
                            "r"(smem_addr(bufB + (sl0 - e0))), "r"(sb) : "memory");
            asm volatile("cp.async.bulk.commit_group;" ::: "memory");
            if (c == 0 && pad) {                                // front edge elems e=0,1 at l=2,3
                out[gstart]     = bufB[2];
                out[gstart + 1] = bufB[3];
            }
            if (c == NC - 1 && !pad) {                          // tail edge elems e=20668,20669
                out[gstart + BF - 2] = bufB[(pad + BF - 2) - e0];
                out[gstart + BF - 1] = bufB[(pad + BF - 1) - e0];
            }
            if (c + NB < NC) {
                // ring slot reuse: the store we just issued reads this slot; drain first
                asm volatile("cp.async.bulk.wait_group 0;" ::: "memory");
                issue_load(c + NB, EF, srcP, srcG, predS, gtS, mbar0);
            }
        }
    }
    if (tid == 0) {
        asm volatile("cp.async.bulk.wait_group 0;" ::: "memory");
    }
}

extern "C" void kernel_launch(void* const* d_in, const int* in_sizes, int n_in,
                              void* d_out, int out_size) {
    const float* pred = (const float*)d_in[0];
    const float* gt   = (const float*)d_in[1];
    float* out = (float*)d_out;
    int B = in_sizes[0] / BF;   // 1024

    cudaFuncSetAttribute(procrustes_l1_kernel,
                         cudaFuncAttributeMaxDynamicSharedMemorySize, SMEM_BYTES);
    procrustes_l1_kernel<<<B, THREADS, SMEM_BYTES>>>(pred, gt, out);
}